// round 2
// baseline (speedup 1.0000x reference)
#include <cuda_runtime.h>
#include <math.h>

#define BN_EPS 1e-5f
#define SPB 32
#define NT 256
#define BPSM 5
#define NSM 148
#define GRID (NSM * BPSM)      /* 740 blocks, guaranteed co-resident */
#define MAXB 65536

// persistent scratch (no allocation allowed)
__device__ float g_zbuf[MAXB * 4];
__device__ float g_part[GRID * 8];
__device__ unsigned g_bar;     // monotone arrival counter (never reset)

__global__ void __launch_bounds__(NT, BPSM) k_fused(
        const float* __restrict__ x,
        const float* __restrict__ enc_w,
        const float* __restrict__ enc_b,
        const float* __restrict__ vp,
        const float* __restrict__ gamma,
        const float* __restrict__ beta,
        float* __restrict__ out,
        int B, int ntiles)
{
    __shared__ float ph[SPB * 194];   // 24832 B: 24 rows x 8 horiz partials, padded
    __shared__ float Us[2 * 16 * 17]; // U re|im, rows padded to 17
    __shared__ float pls[SPB * 17];   // pooled, padded
    __shared__ float encs[68];        // enc_w(64) + enc_b(4)
    __shared__ float zsm[SPB * 4];
    __shared__ float stat[8];

    const int tid = threadIdx.x;

    // ---- stage encoder ----
    if (tid >= 16 && tid < 80) encs[tid - 16] = enc_w[tid - 16];
    if (tid >= 80 && tid < 84) encs[64 + tid - 80] = enc_b[tid - 80];

    // ---- warp 0: build fixed variational unitary U into smem ----
    if (tid < 16) {
        float re[16], im[16];
#pragma unroll
        for (int b = 0; b < 16; b++) { re[b] = (b == tid) ? 1.f : 0.f; im[b] = 0.f; }
#pragma unroll
        for (int d = 0; d < 2; d++) {
#pragma unroll
            for (int w = 0; w < 4; w++) {
                const int mask = 8 >> w;
                float cx, sx, cy, sy, cz, sz;
                __sincosf(0.5f * vp[d * 12 + w * 3 + 0], &sx, &cx);
                __sincosf(0.5f * vp[d * 12 + w * 3 + 1], &sy, &cy);
                __sincosf(0.5f * vp[d * 12 + w * 3 + 2], &sz, &cz);
#pragma unroll
                for (int b = 0; b < 16; b++) {
                    if (b & mask) continue;
                    const int b1 = b | mask;
                    float r0, i0, r1, i1;
                    r0 = re[b]; i0 = im[b]; r1 = re[b1]; i1 = im[b1];
                    re[b]  = cx * r0 + sx * i1;  im[b]  = cx * i0 - sx * r1;
                    re[b1] = cx * r1 + sx * i0;  im[b1] = cx * i1 - sx * r0;
                    r0 = re[b]; i0 = im[b]; r1 = re[b1]; i1 = im[b1];
                    re[b]  = cy * r0 - sy * r1;  im[b]  = cy * i0 - sy * i1;
                    re[b1] = sy * r0 + cy * r1;  im[b1] = sy * i0 + cy * i1;
                    r0 = re[b]; i0 = im[b]; r1 = re[b1]; i1 = im[b1];
                    re[b]  = cz * r0 + sz * i0;  im[b]  = cz * i0 - sz * r0;
                    re[b1] = cz * r1 - sz * i1;  im[b1] = cz * i1 + sz * r1;
                }
            }
#pragma unroll
            for (int c = 0; c < 4; c++) {
                const int tg = (c + 1) & 3;
                const int mc = 8 >> c, mt = 8 >> tg;
#pragma unroll
                for (int b = 0; b < 16; b++) {
                    if ((b & mc) && !(b & mt)) {
                        const int b1 = b | mt;
                        float tr = re[b], ti = im[b];
                        re[b] = re[b1]; im[b] = im[b1];
                        re[b1] = tr;    im[b1] = ti;
                    }
                }
            }
        }
#pragma unroll
        for (int b = 0; b < 16; b++) {
            Us[b * 17 + tid]       = re[b];
            Us[272 + b * 17 + tid] = im[b];
        }
    }

    // per-block BN accumulators (only tid<4 use them)
    float accS = 0.f, accSS = 0.f;

    // ============ persistent tile loop ============
    for (int tile = blockIdx.x; tile < ntiles; tile += GRID) {
        const int samp0 = tile * SPB;
        const int nsamp = min(SPB, B - samp0);
        const float4* x4 = (const float4*)(x + (long)samp0 * 576);
        const int nf4 = nsamp * 144;

        // ---- Phase A: coalesced load + horizontal pool partials ----
#pragma unroll
        for (int k = 0; k < 18; k++) {
            int idx = tid + k * NT;
            if (idx < nf4) {
                float4 v = x4[idx];
                int s   = idx / 144;
                int r   = idx - s * 144;
                int row = r / 6;
                int q   = r - row * 6;
                float lo = v.x + v.y, hi = v.z + v.w;
                int m0 = q + (q > 1) + (q > 4);   // slot for A
                bool straddle = (q == 1) || (q == 4);
                float* dst = ph + s * 194 + row * 8;
                dst[m0] = straddle ? lo : (lo + hi);
                if (straddle) dst[m0 + 1] = hi;
            }
        }
        __syncthreads();

        // ---- Phase B: vertical pooling (window w = slot[2w]+slot[2w+1]) ----
#pragma unroll
        for (int k = 0; k < 2; k++) {
            int o = tid + k * NT;
            int s = o >> 4, w = o & 15;
            if (s < nsamp) {
                int wy = w >> 2, wx = w & 3;
                const float* pb = ph + s * 194 + wy * 48;
                float sum = 0.f;
#pragma unroll
                for (int dy = 0; dy < 6; dy++)
                    sum += pb[dy * 8 + 2 * wx] + pb[dy * 8 + 2 * wx + 1];
                pls[s * 17 + w] = sum * (1.f / 36.f);
            }
        }
        __syncthreads();

        // ---- Phase C: circuit, 8 threads / sample ----
        const int s = tid >> 3;
        const int j = tid & 7;
        const int samp = samp0 + s;
        float z0 = 0.f, z1 = 0.f, z2 = 0.f, z3 = 0.f;
        if (samp < B) {
            float ang[4];
#pragma unroll
            for (int i = 0; i < 4; i++) {
                float a = encs[64 + i];
#pragma unroll
                for (int kk = 0; kk < 16; kk++)
                    a = fmaf(encs[i * 16 + kk], pls[s * 17 + kk], a);
                ang[i] = a;
            }
            float cc[4], ss[4];
#pragma unroll
            for (int i = 0; i < 4; i++) __sincosf(0.5f * ang[i], &ss[i], &cc[i]);

            // |psi_b| = prod_i (bit ? s_i : c_i); phase (-i)^popc(b) folded below
            float p01[4], p23[4];
            p01[0] = cc[0] * cc[1]; p01[1] = cc[0] * ss[1];
            p01[2] = ss[0] * cc[1]; p01[3] = ss[0] * ss[1];
            p23[0] = cc[2] * cc[3]; p23[1] = cc[2] * ss[3];
            p23[2] = ss[2] * cc[3]; p23[3] = ss[2] * ss[3];
            float v[16];
#pragma unroll
            for (int b = 0; b < 16; b++) v[b] = p01[b >> 2] * p23[b & 3];

            // two rows of U @ psi; (-i)^popc(t) handled at compile time
            const int r0 = 2 * j, r1 = 2 * j + 1;
            const float* ur = Us;
            const float* ui = Us + 272;
            float ar0 = 0.f, ai0 = 0.f, ar1 = 0.f, ai1 = 0.f;
#pragma unroll
            for (int t = 0; t < 16; t++) {
                float u0r = ur[r0 * 17 + t], u0i = ui[r0 * 17 + t];
                float u1r = ur[r1 * 17 + t], u1i = ui[r1 * 17 + t];
                const int k4 = __popc(t) & 3;
                if (k4 == 0) {
                    ar0 = fmaf(u0r, v[t], ar0); ai0 = fmaf(u0i, v[t], ai0);
                    ar1 = fmaf(u1r, v[t], ar1); ai1 = fmaf(u1i, v[t], ai1);
                } else if (k4 == 1) {
                    ar0 = fmaf(u0i, v[t], ar0); ai0 = fmaf(-u0r, v[t], ai0);
                    ar1 = fmaf(u1i, v[t], ar1); ai1 = fmaf(-u1r, v[t], ai1);
                } else if (k4 == 2) {
                    ar0 = fmaf(-u0r, v[t], ar0); ai0 = fmaf(-u0i, v[t], ai0);
                    ar1 = fmaf(-u1r, v[t], ar1); ai1 = fmaf(-u1i, v[t], ai1);
                } else {
                    ar0 = fmaf(-u0i, v[t], ar0); ai0 = fmaf(u0r, v[t], ai0);
                    ar1 = fmaf(-u1i, v[t], ar1); ai1 = fmaf(u1r, v[t], ai1);
                }
            }
            float p0 = ar0 * ar0 + ai0 * ai0;
            float p1 = ar1 * ar1 + ai1 * ai1;
            z0 = ((r0 & 8) ? -p0 : p0) + ((r1 & 8) ? -p1 : p1);
            z1 = ((r0 & 4) ? -p0 : p0) + ((r1 & 4) ? -p1 : p1);
            z2 = ((r0 & 2) ? -p0 : p0) + ((r1 & 2) ? -p1 : p1);
            z3 = p0 - p1;
        }
#pragma unroll
        for (int off = 4; off >= 1; off >>= 1) {
            z0 += __shfl_down_sync(0xffffffffu, z0, off);
            z1 += __shfl_down_sync(0xffffffffu, z1, off);
            z2 += __shfl_down_sync(0xffffffffu, z2, off);
            z3 += __shfl_down_sync(0xffffffffu, z3, off);
        }
        if (j == 0) {
            zsm[s * 4 + 0] = z0; zsm[s * 4 + 1] = z1;
            zsm[s * 4 + 2] = z2; zsm[s * 4 + 3] = z3;
            if (samp < B)
                ((float4*)g_zbuf)[samp] = make_float4(z0, z1, z2, z3);
        }
        __syncthreads();

        // ---- accumulate BN partials (deterministic fixed order) ----
        if (tid < 4) {
#pragma unroll
            for (int g = 0; g < SPB; g++) {
                float zv = zsm[g * 4 + tid];
                accS += zv; accSS += zv * zv;
            }
        }
    }

    // ---- publish partials + grid barrier ----
    if (tid < 4) {
        g_part[blockIdx.x * 8 + tid]     = accS;
        g_part[blockIdx.x * 8 + 4 + tid] = accSS;
    }
    __threadfence();
    __syncthreads();
    if (tid == 0) {
        unsigned arr = atomicAdd(&g_bar, 1u) + 1u;
        unsigned target = ((arr + GRID - 1u) / GRID) * GRID;  // this launch's release
        while (*((volatile unsigned*)&g_bar) < target) {}
        __threadfence();
    }
    __syncthreads();

    // ---- redundant-but-deterministic stats reduction (each block) ----
    {
        float* red = ph;   // reuse smem
        const int w = tid & 7, r = tid >> 3;
        float S = 0.f;
        for (int i = r; i < GRID; i += 32) S += g_part[i * 8 + w];
        red[tid] = S;
        __syncthreads();
#pragma unroll
        for (int step = 128; step >= 8; step >>= 1) {
            if (tid < step) red[tid] += red[tid + step];
            __syncthreads();
        }
        if (tid < 4) {
            float mean = red[tid] / (float)B;
            float var  = red[4 + tid] / (float)B - mean * mean;
            float sc   = gamma[tid] * rsqrtf(var + BN_EPS);
            stat[tid]     = sc;
            stat[4 + tid] = beta[tid] - mean * sc;
        }
        __syncthreads();
    }

    // ---- normalize (z is L2-resident) ----
    const float s0 = stat[0], s1 = stat[1], s2 = stat[2], s3 = stat[3];
    const float h0 = stat[4], h1 = stat[5], h2 = stat[6], h3 = stat[7];
    for (int b = blockIdx.x * NT + tid; b < B; b += GRID * NT) {
        float4 z = ((const float4*)g_zbuf)[b];
        ((float4*)out)[b] = make_float4(fmaf(z.x, s0, h0), fmaf(z.y, s1, h1),
                                        fmaf(z.z, s2, h2), fmaf(z.w, s3, h3));
    }
}

extern "C" void kernel_launch(void* const* d_in, const int* in_sizes, int n_in,
                              void* d_out, int out_size)
{
    const float* x      = (const float*)d_in[0];
    const float* enc_w  = (const float*)d_in[1];
    const float* enc_b  = (const float*)d_in[2];
    const float* vp     = (const float*)d_in[3];
    const float* gamma  = (const float*)d_in[4];
    const float* beta   = (const float*)d_in[5];

    const int B      = in_sizes[0] / 576;   // [B,1,24,24]
    const int ntiles = (B + SPB - 1) / SPB;

    k_fused<<<GRID, NT>>>(x, enc_w, enc_b, vp, gamma, beta,
                          (float*)d_out, B, ntiles);
}

// round 3
// speedup vs baseline: 1.3255x; 1.3255x over previous
#include <cuda_runtime.h>
#include <math.h>

#define BN_EPS 1e-5f
#define SPB 32
#define NT 576                 /* 4 * 144: per-thread x-offset is loop-invariant */
#define BPSM 2
#define NSM 148
#define GRID (NSM * BPSM)      /* 296 blocks, guaranteed co-resident */
#define MAXB 65536

// persistent scratch (no allocation allowed)
__device__ float g_zbuf[MAXB * 4];
__device__ float g_part[GRID * 8];
__device__ unsigned g_bar;     // monotone arrival counter (never reset)

__global__ void __launch_bounds__(NT, BPSM) k_fused(
        const float* __restrict__ x,
        const float* __restrict__ enc_w,
        const float* __restrict__ enc_b,
        const float* __restrict__ vp,
        const float* __restrict__ gamma,
        const float* __restrict__ beta,
        float* __restrict__ out,
        int B, int ntiles)
{
    __shared__ float ph[SPB * 194];   // 24832 B staging: 24 rows x 8 slots, padded
    __shared__ float Us[2 * 16 * 17]; // U re|im, rows padded to 17
    __shared__ float pls[SPB * 17];   // pooled, padded
    __shared__ float encs[68];        // enc_w(64) + enc_b(4)
    __shared__ float zsm[SPB * 4];
    __shared__ float stat[8];

    const int tid = threadIdx.x;

    // ---- stage encoder ----
    if (tid >= 32 && tid < 96)  encs[tid - 32] = enc_w[tid - 32];
    if (tid >= 96 && tid < 100) encs[64 + tid - 96] = enc_b[tid - 96];

    // ---- warp 0: build fixed variational unitary U into smem ----
    if (tid < 16) {
        float re[16], im[16];
#pragma unroll
        for (int b = 0; b < 16; b++) { re[b] = (b == tid) ? 1.f : 0.f; im[b] = 0.f; }
#pragma unroll
        for (int d = 0; d < 2; d++) {
#pragma unroll
            for (int w = 0; w < 4; w++) {
                const int mask = 8 >> w;
                float cx, sx, cy, sy, cz, sz;
                sincosf(0.5f * vp[d * 12 + w * 3 + 0], &sx, &cx);
                sincosf(0.5f * vp[d * 12 + w * 3 + 1], &sy, &cy);
                sincosf(0.5f * vp[d * 12 + w * 3 + 2], &sz, &cz);
#pragma unroll
                for (int b = 0; b < 16; b++) {
                    if (b & mask) continue;
                    const int b1 = b | mask;
                    float r0, i0, r1, i1;
                    r0 = re[b]; i0 = im[b]; r1 = re[b1]; i1 = im[b1];
                    re[b]  = cx * r0 + sx * i1;  im[b]  = cx * i0 - sx * r1;
                    re[b1] = cx * r1 + sx * i0;  im[b1] = cx * i1 - sx * r0;
                    r0 = re[b]; i0 = im[b]; r1 = re[b1]; i1 = im[b1];
                    re[b]  = cy * r0 - sy * r1;  im[b]  = cy * i0 - sy * i1;
                    re[b1] = sy * r0 + cy * r1;  im[b1] = sy * i0 + cy * i1;
                    r0 = re[b]; i0 = im[b]; r1 = re[b1]; i1 = im[b1];
                    re[b]  = cz * r0 + sz * i0;  im[b]  = cz * i0 - sz * r0;
                    re[b1] = cz * r1 - sz * i1;  im[b1] = cz * i1 + sz * r1;
                }
            }
#pragma unroll
            for (int c = 0; c < 4; c++) {
                const int tg = (c + 1) & 3;
                const int mc = 8 >> c, mt = 8 >> tg;
#pragma unroll
                for (int b = 0; b < 16; b++) {
                    if ((b & mc) && !(b & mt)) {
                        const int b1 = b | mt;
                        float tr = re[b], ti = im[b];
                        re[b] = re[b1]; im[b] = im[b1];
                        re[b1] = tr;    im[b1] = ti;
                    }
                }
            }
        }
#pragma unroll
        for (int b = 0; b < 16; b++) {
            Us[b * 17 + tid]       = re[b];
            Us[272 + b * 17 + tid] = im[b];
        }
    }

    // ---- loop-invariant Phase-A decomposition ----
    const int r   = tid % 144;        // float4 offset within a sample
    const int sb  = tid / 144;        // 0..3  (sample sub-slot)
    const int row = r / 6;
    const int q   = r - row * 6;
    const int m0  = q + (q > 1) + (q > 4);
    const bool strad = (q == 1) || (q == 4);
    float* const dst0 = ph + row * 8 + m0;   // + s*194 at use

    // per-block BN accumulators (only tid<4 use them)
    float accS = 0.f, accSS = 0.f;

    // ============ persistent tile loop ============
    for (int tile = blockIdx.x; tile < ntiles; tile += GRID) {
        const int samp0 = tile * SPB;
        const int nsamp = min(SPB, B - samp0);
        const float4* x4 = (const float4*)(x + (long)samp0 * 576);

        // ---- Phase A: 8 address-constant LDG.128, then reduce+store ----
        if (nsamp == SPB) {
            float4 vv[8];
#pragma unroll
            for (int k = 0; k < 8; k++)
                vv[k] = __ldcs(x4 + (size_t)(sb + 4 * k) * 144 + r);
#pragma unroll
            for (int k = 0; k < 8; k++) {
                const int s = sb + 4 * k;
                float lo = vv[k].x + vv[k].y, hi = vv[k].z + vv[k].w;
                float* d = dst0 + s * 194;
                d[0] = strad ? lo : (lo + hi);
                if (strad) d[1] = hi;
            }
        } else {
#pragma unroll
            for (int k = 0; k < 8; k++) {
                const int s = sb + 4 * k;
                if (s < nsamp) {
                    float4 v = __ldcs(x4 + (size_t)s * 144 + r);
                    float lo = v.x + v.y, hi = v.z + v.w;
                    float* d = dst0 + s * 194;
                    d[0] = strad ? lo : (lo + hi);
                    if (strad) d[1] = hi;
                }
            }
        }
        __syncthreads();

        // ---- Phase B: vertical pooling, one window per thread (512 used) ----
        {
            int s = tid >> 4, w = tid & 15;
            if (tid < 512 && s < nsamp) {
                int wy = w >> 2, wx = w & 3;
                const float* pb = ph + s * 194 + wy * 48;
                float sum = 0.f;
#pragma unroll
                for (int dy = 0; dy < 6; dy++)
                    sum += pb[dy * 8 + 2 * wx] + pb[dy * 8 + 2 * wx + 1];
                pls[s * 17 + w] = sum * (1.f / 36.f);
            }
        }
        __syncthreads();

        // ---- Phase C: circuit, 8 threads / sample (threads 0..255) ----
        const int s = tid >> 3;
        const int j = tid & 7;
        const int samp = samp0 + s;
        float z0 = 0.f, z1 = 0.f, z2 = 0.f, z3 = 0.f;
        if (tid < 256 && samp < B) {
            float ang[4];
#pragma unroll
            for (int i = 0; i < 4; i++) {
                float a = encs[64 + i];
#pragma unroll
                for (int kk = 0; kk < 16; kk++)
                    a = fmaf(encs[i * 16 + kk], pls[s * 17 + kk], a);
                ang[i] = a;
            }
            float cc[4], ss[4];
#pragma unroll
            for (int i = 0; i < 4; i++) sincosf(0.5f * ang[i], &ss[i], &cc[i]);

            float p01[4], p23[4];
            p01[0] = cc[0] * cc[1]; p01[1] = cc[0] * ss[1];
            p01[2] = ss[0] * cc[1]; p01[3] = ss[0] * ss[1];
            p23[0] = cc[2] * cc[3]; p23[1] = cc[2] * ss[3];
            p23[2] = ss[2] * cc[3]; p23[3] = ss[2] * ss[3];
            float v[16];
#pragma unroll
            for (int b = 0; b < 16; b++) v[b] = p01[b >> 2] * p23[b & 3];

            const int r0 = 2 * j, r1 = 2 * j + 1;
            const float* ur = Us;
            const float* ui = Us + 272;
            float ar0 = 0.f, ai0 = 0.f, ar1 = 0.f, ai1 = 0.f;
#pragma unroll
            for (int t = 0; t < 16; t++) {
                float u0r = ur[r0 * 17 + t], u0i = ui[r0 * 17 + t];
                float u1r = ur[r1 * 17 + t], u1i = ui[r1 * 17 + t];
                const int k4 = __popc(t) & 3;
                if (k4 == 0) {
                    ar0 = fmaf(u0r, v[t], ar0); ai0 = fmaf(u0i, v[t], ai0);
                    ar1 = fmaf(u1r, v[t], ar1); ai1 = fmaf(u1i, v[t], ai1);
                } else if (k4 == 1) {
                    ar0 = fmaf(u0i, v[t], ar0); ai0 = fmaf(-u0r, v[t], ai0);
                    ar1 = fmaf(u1i, v[t], ar1); ai1 = fmaf(-u1r, v[t], ai1);
                } else if (k4 == 2) {
                    ar0 = fmaf(-u0r, v[t], ar0); ai0 = fmaf(-u0i, v[t], ai0);
                    ar1 = fmaf(-u1r, v[t], ar1); ai1 = fmaf(-u1i, v[t], ai1);
                } else {
                    ar0 = fmaf(-u0i, v[t], ar0); ai0 = fmaf(u0r, v[t], ai0);
                    ar1 = fmaf(-u1i, v[t], ar1); ai1 = fmaf(u1r, v[t], ai1);
                }
            }
            float p0 = ar0 * ar0 + ai0 * ai0;
            float p1 = ar1 * ar1 + ai1 * ai1;
            z0 = ((r0 & 8) ? -p0 : p0) + ((r1 & 8) ? -p1 : p1);
            z1 = ((r0 & 4) ? -p0 : p0) + ((r1 & 4) ? -p1 : p1);
            z2 = ((r0 & 2) ? -p0 : p0) + ((r1 & 2) ? -p1 : p1);
            z3 = p0 - p1;
        }
#pragma unroll
        for (int off = 4; off >= 1; off >>= 1) {
            z0 += __shfl_down_sync(0xffffffffu, z0, off);
            z1 += __shfl_down_sync(0xffffffffu, z1, off);
            z2 += __shfl_down_sync(0xffffffffu, z2, off);
            z3 += __shfl_down_sync(0xffffffffu, z3, off);
        }
        if (tid < 256 && j == 0) {
            zsm[s * 4 + 0] = z0; zsm[s * 4 + 1] = z1;
            zsm[s * 4 + 2] = z2; zsm[s * 4 + 3] = z3;
            if (samp < B)
                ((float4*)g_zbuf)[samp] = make_float4(z0, z1, z2, z3);
        }
        __syncthreads();

        // ---- accumulate BN partials (deterministic fixed order) ----
        if (tid < 4) {
            const int lim = nsamp;
            for (int g = 0; g < lim; g++) {
                float zv = zsm[g * 4 + tid];
                accS += zv; accSS += zv * zv;
            }
        }
        __syncthreads();
    }

    // ---- publish partials + grid barrier ----
    if (tid < 4) {
        g_part[blockIdx.x * 8 + tid]     = accS;
        g_part[blockIdx.x * 8 + 4 + tid] = accSS;
    }
    __threadfence();
    __syncthreads();
    if (tid == 0) {
        unsigned arr = atomicAdd(&g_bar, 1u) + 1u;
        unsigned target = ((arr + GRID - 1u) / GRID) * GRID;  // this launch's release
        while (*((volatile unsigned*)&g_bar) < target) {}
        __threadfence();
    }
    __syncthreads();

    // ---- redundant-but-deterministic stats reduction (each block) ----
    {
        float* red = ph;   // reuse smem
        const int w = tid & 7, rr = tid >> 3;
        float S = 0.f;
        if (tid < 256)
            for (int i = rr; i < GRID; i += 32) S += g_part[i * 8 + w];
        if (tid < 256) red[tid] = S;
        __syncthreads();
#pragma unroll
        for (int step = 128; step >= 8; step >>= 1) {
            if (tid < step) red[tid] += red[tid + step];
            __syncthreads();
        }
        if (tid < 4) {
            float mean = red[tid] / (float)B;
            float var  = red[4 + tid] / (float)B - mean * mean;
            float sc   = gamma[tid] * rsqrtf(var + BN_EPS);
            stat[tid]     = sc;
            stat[4 + tid] = beta[tid] - mean * sc;
        }
        __syncthreads();
    }

    // ---- normalize (z is L2-resident) ----
    const float s0 = stat[0], s1 = stat[1], s2 = stat[2], s3 = stat[3];
    const float h0 = stat[4], h1 = stat[5], h2 = stat[6], h3 = stat[7];
    for (int b = blockIdx.x * NT + tid; b < B; b += GRID * NT) {
        float4 z = ((const float4*)g_zbuf)[b];
        ((float4*)out)[b] = make_float4(fmaf(z.x, s0, h0), fmaf(z.y, s1, h1),
                                        fmaf(z.z, s2, h2), fmaf(z.w, s3, h3));
    }
}

extern "C" void kernel_launch(void* const* d_in, const int* in_sizes, int n_in,
                              void* d_out, int out_size)
{
    const float* x      = (const float*)d_in[0];
    const float* enc_w  = (const float*)d_in[1];
    const float* enc_b  = (const float*)d_in[2];
    const float* vp     = (const float*)d_in[3];
    const float* gamma  = (const float*)d_in[4];
    const float* beta   = (const float*)d_in[5];

    const int B      = in_sizes[0] / 576;   // [B,1,24,24]
    const int ntiles = (B + SPB - 1) / SPB;

    k_fused<<<GRID, NT>>>(x, enc_w, enc_b, vp, gamma, beta,
                          (float*)d_out, B, ntiles);
}

// round 4
// speedup vs baseline: 1.5208x; 1.1474x over previous
#include <cuda_runtime.h>
#include <math.h>

#define BN_EPS 1e-5f
#define SPB 16
#define NT 288                 /* 2 * 144: per-thread x-offset is loop-invariant */
#define BPSM 2
#define NSM 148
#define GRID (NSM * BPSM)      /* 296 blocks, guaranteed co-resident */
#define MAXB 65536

// persistent scratch (no allocation allowed)
__device__ float g_zbuf[MAXB * 4];
__device__ float g_part[GRID * 8];
__device__ unsigned g_bar;     // monotone arrival counter (never reset)

__global__ void __launch_bounds__(NT, BPSM) k_fused(
        const float* __restrict__ x,
        const float* __restrict__ enc_w,
        const float* __restrict__ enc_b,
        const float* __restrict__ vp,
        const float* __restrict__ gamma,
        const float* __restrict__ beta,
        float* __restrict__ out,
        int B, int ntiles)
{
    __shared__ float ph[SPB * 194];   // 12416 B staging: 24 rows x 8 slots, padded
    __shared__ float Us[2 * 16 * 17]; // U re|im, rows padded to 17
    __shared__ float pls[SPB * 17];   // pooled, padded
    __shared__ float encs[68];        // enc_w(64) + enc_b(4)
    __shared__ float zsm[SPB * 4];
    __shared__ float stat[8];

    const int tid = threadIdx.x;

    // ---- stage encoder ----
    if (tid >= 32 && tid < 96)  encs[tid - 32] = enc_w[tid - 32];
    if (tid >= 96 && tid < 100) encs[64 + tid - 96] = enc_b[tid - 96];

    // ---- warp 0: build fixed variational unitary U into smem ----
    if (tid < 16) {
        float re[16], im[16];
#pragma unroll
        for (int b = 0; b < 16; b++) { re[b] = (b == tid) ? 1.f : 0.f; im[b] = 0.f; }
#pragma unroll
        for (int d = 0; d < 2; d++) {
#pragma unroll
            for (int w = 0; w < 4; w++) {
                const int mask = 8 >> w;
                float cx, sx, cy, sy, cz, sz;
                sincosf(0.5f * vp[d * 12 + w * 3 + 0], &sx, &cx);
                sincosf(0.5f * vp[d * 12 + w * 3 + 1], &sy, &cy);
                sincosf(0.5f * vp[d * 12 + w * 3 + 2], &sz, &cz);
#pragma unroll
                for (int b = 0; b < 16; b++) {
                    if (b & mask) continue;
                    const int b1 = b | mask;
                    float r0, i0, r1, i1;
                    r0 = re[b]; i0 = im[b]; r1 = re[b1]; i1 = im[b1];
                    re[b]  = cx * r0 + sx * i1;  im[b]  = cx * i0 - sx * r1;
                    re[b1] = cx * r1 + sx * i0;  im[b1] = cx * i1 - sx * r0;
                    r0 = re[b]; i0 = im[b]; r1 = re[b1]; i1 = im[b1];
                    re[b]  = cy * r0 - sy * r1;  im[b]  = cy * i0 - sy * i1;
                    re[b1] = sy * r0 + cy * r1;  im[b1] = sy * i0 + cy * i1;
                    r0 = re[b]; i0 = im[b]; r1 = re[b1]; i1 = im[b1];
                    re[b]  = cz * r0 + sz * i0;  im[b]  = cz * i0 - sz * r0;
                    re[b1] = cz * r1 - sz * i1;  im[b1] = cz * i1 + sz * r1;
                }
            }
#pragma unroll
            for (int c = 0; c < 4; c++) {
                const int tg = (c + 1) & 3;
                const int mc = 8 >> c, mt = 8 >> tg;
#pragma unroll
                for (int b = 0; b < 16; b++) {
                    if ((b & mc) && !(b & mt)) {
                        const int b1 = b | mt;
                        float tr = re[b], ti = im[b];
                        re[b] = re[b1]; im[b] = im[b1];
                        re[b1] = tr;    im[b1] = ti;
                    }
                }
            }
        }
#pragma unroll
        for (int b = 0; b < 16; b++) {
            Us[b * 17 + tid]       = re[b];
            Us[272 + b * 17 + tid] = im[b];
        }
    }

    // ---- loop-invariant Phase-A decomposition ----
    const int r   = tid % 144;        // float4 offset within a sample
    const int sb  = tid / 144;        // 0..1  (sample sub-slot)
    const int row = r / 6;
    const int q   = r - row * 6;
    const int m0  = q + (q > 1) + (q > 4);
    const bool strad = (q == 1) || (q == 4);
    float* const dst0 = ph + row * 8 + m0;   // + s*194 at use

    // per-block BN accumulators (only tid<4 use them)
    float accS = 0.f, accSS = 0.f;

    // ---- prefetch first tile ----
    float4 vv[8];
    {
        int tile = blockIdx.x;
        if (tile < ntiles) {
            const int samp0 = tile * SPB;
            const int ns = min(SPB, B - samp0);
            const float4* x4 = (const float4*)(x + (long)samp0 * 576);
#pragma unroll
            for (int k = 0; k < 8; k++) {
                const int s = sb + 2 * k;
                if (s < ns) vv[k] = __ldcs(x4 + (size_t)s * 144 + r);
            }
        }
    }

    // ============ persistent tile loop (software-pipelined) ============
    for (int tile = blockIdx.x; tile < ntiles; tile += GRID) {
        const int samp0 = tile * SPB;
        const int nsamp = min(SPB, B - samp0);

        // ---- Phase A-store: commit prefetched registers to smem ----
#pragma unroll
        for (int k = 0; k < 8; k++) {
            const int s = sb + 2 * k;
            if (s < nsamp) {
                float lo = vv[k].x + vv[k].y, hi = vv[k].z + vv[k].w;
                float* d = dst0 + s * 194;
                d[0] = strad ? lo : (lo + hi);
                if (strad) d[1] = hi;
            }
        }

        // ---- prefetch NEXT tile (loads overlap compute below) ----
        {
            const int tile2 = tile + GRID;
            if (tile2 < ntiles) {
                const int samp2 = tile2 * SPB;
                const int ns2 = min(SPB, B - samp2);
                const float4* x4n = (const float4*)(x + (long)samp2 * 576);
#pragma unroll
                for (int k = 0; k < 8; k++) {
                    const int s = sb + 2 * k;
                    if (s < ns2) vv[k] = __ldcs(x4n + (size_t)s * 144 + r);
                }
            }
        }
        __syncthreads();

        // ---- Phase B: vertical pooling, one window per thread (256 used) ----
        {
            int s = tid >> 4, w = tid & 15;
            if (tid < 256 && s < nsamp) {
                int wy = w >> 2, wx = w & 3;
                const float* pb = ph + s * 194 + wy * 48;
                float sum = 0.f;
#pragma unroll
                for (int dy = 0; dy < 6; dy++)
                    sum += pb[dy * 8 + 2 * wx] + pb[dy * 8 + 2 * wx + 1];
                pls[s * 17 + w] = sum * (1.f / 36.f);
            }
        }
        __syncthreads();

        // ---- Phase C: circuit, 8 threads / sample (threads 0..127) ----
        const int s = tid >> 3;
        const int j = tid & 7;
        const int samp = samp0 + s;
        float z0 = 0.f, z1 = 0.f, z2 = 0.f, z3 = 0.f;
        if (tid < 128 && samp < B) {
            float ang[4];
#pragma unroll
            for (int i = 0; i < 4; i++) {
                float a = encs[64 + i];
#pragma unroll
                for (int kk = 0; kk < 16; kk++)
                    a = fmaf(encs[i * 16 + kk], pls[s * 17 + kk], a);
                ang[i] = a;
            }
            float cc[4], ss[4];
#pragma unroll
            for (int i = 0; i < 4; i++) __sincosf(0.5f * ang[i], &ss[i], &cc[i]);

            float p01[4], p23[4];
            p01[0] = cc[0] * cc[1]; p01[1] = cc[0] * ss[1];
            p01[2] = ss[0] * cc[1]; p01[3] = ss[0] * ss[1];
            p23[0] = cc[2] * cc[3]; p23[1] = cc[2] * ss[3];
            p23[2] = ss[2] * cc[3]; p23[3] = ss[2] * ss[3];
            float v[16];
#pragma unroll
            for (int b = 0; b < 16; b++) v[b] = p01[b >> 2] * p23[b & 3];

            const int r0 = 2 * j, r1 = 2 * j + 1;
            const float* ur = Us;
            const float* ui = Us + 272;
            float ar0 = 0.f, ai0 = 0.f, ar1 = 0.f, ai1 = 0.f;
#pragma unroll
            for (int t = 0; t < 16; t++) {
                float u0r = ur[r0 * 17 + t], u0i = ui[r0 * 17 + t];
                float u1r = ur[r1 * 17 + t], u1i = ui[r1 * 17 + t];
                const int k4 = __popc(t) & 3;
                if (k4 == 0) {
                    ar0 = fmaf(u0r, v[t], ar0); ai0 = fmaf(u0i, v[t], ai0);
                    ar1 = fmaf(u1r, v[t], ar1); ai1 = fmaf(u1i, v[t], ai1);
                } else if (k4 == 1) {
                    ar0 = fmaf(u0i, v[t], ar0); ai0 = fmaf(-u0r, v[t], ai0);
                    ar1 = fmaf(u1i, v[t], ar1); ai1 = fmaf(-u1r, v[t], ai1);
                } else if (k4 == 2) {
                    ar0 = fmaf(-u0r, v[t], ar0); ai0 = fmaf(-u0i, v[t], ai0);
                    ar1 = fmaf(-u1r, v[t], ar1); ai1 = fmaf(-u1i, v[t], ai1);
                } else {
                    ar0 = fmaf(-u0i, v[t], ar0); ai0 = fmaf(u0r, v[t], ai0);
                    ar1 = fmaf(-u1i, v[t], ar1); ai1 = fmaf(u1r, v[t], ai1);
                }
            }
            float p0 = ar0 * ar0 + ai0 * ai0;
            float p1 = ar1 * ar1 + ai1 * ai1;
            z0 = ((r0 & 8) ? -p0 : p0) + ((r1 & 8) ? -p1 : p1);
            z1 = ((r0 & 4) ? -p0 : p0) + ((r1 & 4) ? -p1 : p1);
            z2 = ((r0 & 2) ? -p0 : p0) + ((r1 & 2) ? -p1 : p1);
            z3 = p0 - p1;
        }
#pragma unroll
        for (int off = 4; off >= 1; off >>= 1) {
            z0 += __shfl_down_sync(0xffffffffu, z0, off);
            z1 += __shfl_down_sync(0xffffffffu, z1, off);
            z2 += __shfl_down_sync(0xffffffffu, z2, off);
            z3 += __shfl_down_sync(0xffffffffu, z3, off);
        }
        if (tid < 128 && j == 0) {
            zsm[s * 4 + 0] = z0; zsm[s * 4 + 1] = z1;
            zsm[s * 4 + 2] = z2; zsm[s * 4 + 3] = z3;
            if (samp < B)
                ((float4*)g_zbuf)[samp] = make_float4(z0, z1, z2, z3);
        }
        __syncthreads();

        // ---- accumulate BN partials (deterministic fixed order) ----
        if (tid < 4) {
            for (int g = 0; g < nsamp; g++) {
                float zv = zsm[g * 4 + tid];
                accS += zv; accSS += zv * zv;
            }
        }
        __syncthreads();
    }

    // ---- publish partials + grid barrier ----
    if (tid < 4) {
        g_part[blockIdx.x * 8 + tid]     = accS;
        g_part[blockIdx.x * 8 + 4 + tid] = accSS;
    }
    __threadfence();
    __syncthreads();
    if (tid == 0) {
        unsigned arr = atomicAdd(&g_bar, 1u) + 1u;
        unsigned target = ((arr + GRID - 1u) / GRID) * GRID;  // this launch's release
        while (*((volatile unsigned*)&g_bar) < target) {}
        __threadfence();
    }
    __syncthreads();

    // ---- redundant-but-deterministic stats reduction (each block) ----
    {
        float* red = ph;   // reuse smem
        const int w = tid & 7, rr = tid >> 3;
        float S = 0.f;
        if (tid < 256)
            for (int i = rr; i < GRID; i += 32) S += g_part[i * 8 + w];
        if (tid < 256) red[tid] = S;
        __syncthreads();
#pragma unroll
        for (int step = 128; step >= 8; step >>= 1) {
            if (tid < step) red[tid] += red[tid + step];
            __syncthreads();
        }
        if (tid < 4) {
            float mean = red[tid] / (float)B;
            float var  = red[4 + tid] / (float)B - mean * mean;
            float sc   = gamma[tid] * rsqrtf(var + BN_EPS);
            stat[tid]     = sc;
            stat[4 + tid] = beta[tid] - mean * sc;
        }
        __syncthreads();
    }

    // ---- normalize (z is L2-resident) ----
    const float s0 = stat[0], s1 = stat[1], s2 = stat[2], s3 = stat[3];
    const float h0 = stat[4], h1 = stat[5], h2 = stat[6], h3 = stat[7];
    for (int b = blockIdx.x * NT + tid; b < B; b += GRID * NT) {
        float4 z = ((const float4*)g_zbuf)[b];
        ((float4*)out)[b] = make_float4(fmaf(z.x, s0, h0), fmaf(z.y, s1, h1),
                                        fmaf(z.z, s2, h2), fmaf(z.w, s3, h3));
    }
}

extern "C" void kernel_launch(void* const* d_in, const int* in_sizes, int n_in,
                              void* d_out, int out_size)
{
    const float* x      = (const float*)d_in[0];
    const float* enc_w  = (const float*)d_in[1];
    const float* enc_b  = (const float*)d_in[2];
    const float* vp     = (const float*)d_in[3];
    const float* gamma  = (const float*)d_in[4];
    const float* beta   = (const float*)d_in[5];

    const int B      = in_sizes[0] / 576;   // [B,1,24,24]
    const int ntiles = (B + SPB - 1) / SPB;

    k_fused<<<GRID, NT>>>(x, enc_w, enc_b, vp, gamma, beta,
                          (float*)d_out, B, ntiles);
}

// round 5
// speedup vs baseline: 1.5374x; 1.0109x over previous
#include <cuda_runtime.h>
#include <math.h>
#include <stdint.h>

#define BN_EPS 1e-5f
#define SPB 8                  /* samples per tile */
#define NT 256
#define BPSM 3
#define NSM 148
#define GRID (NSM * BPSM)      /* 444 blocks, guaranteed co-resident */
#define MAXB 65536
#define TILE_FLOATS (SPB * 576)
#define TILE_BYTES  (TILE_FLOATS * 4)   /* 18432 */

// persistent scratch (no allocation allowed)
__device__ float g_zbuf[MAXB * 4];
__device__ float g_part[GRID * 8];
__device__ unsigned g_bar;     // monotone arrival counter (never reset)

__device__ __forceinline__ uint32_t smem_u32(const void* p) {
    uint32_t a;
    asm("{ .reg .u64 t; cvta.to.shared.u64 t, %1; cvt.u32.u64 %0, t; }"
        : "=r"(a) : "l"(p));
    return a;
}
__device__ __forceinline__ void mbar_init(uint32_t m, uint32_t cnt) {
    asm volatile("mbarrier.init.shared.b64 [%0], %1;" :: "r"(m), "r"(cnt) : "memory");
}
__device__ __forceinline__ void mbar_expect_tx(uint32_t m, uint32_t bytes) {
    asm volatile("mbarrier.arrive.expect_tx.shared.b64 _, [%0], %1;"
                 :: "r"(m), "r"(bytes) : "memory");
}
__device__ __forceinline__ void bulk_ld(uint32_t dst, const void* src,
                                        uint32_t bytes, uint32_t m) {
    asm volatile("cp.async.bulk.shared::cluster.global.mbarrier::complete_tx::bytes "
                 "[%0], [%1], %2, [%3];"
                 :: "r"(dst), "l"(src), "r"(bytes), "r"(m) : "memory");
}
__device__ __forceinline__ void mbar_wait(uint32_t m, uint32_t phase) {
    uint32_t done;
    asm volatile("{\n\t.reg .pred p;\n\t"
                 "mbarrier.try_wait.parity.acquire.cta.shared::cta.b64 p, [%1], %2;\n\t"
                 "selp.b32 %0, 1, 0, p;\n\t}"
                 : "=r"(done) : "r"(m), "r"(phase) : "memory");
    if (!done) {
        asm volatile("{\n\t.reg .pred P1;\n\t"
                     "W_%=:\n\t"
                     "mbarrier.try_wait.parity.acquire.cta.shared::cta.b64 P1, [%0], %1, 0x989680;\n\t"
                     "@P1 bra.uni D_%=;\n\t"
                     "bra.uni W_%=;\n\t"
                     "D_%=:\n\t}" :: "r"(m), "r"(phase) : "memory");
    }
}

__global__ void __launch_bounds__(NT, BPSM) k_fused(
        const float* __restrict__ x,
        const float* __restrict__ enc_w,
        const float* __restrict__ enc_b,
        const float* __restrict__ vp,
        const float* __restrict__ gamma,
        const float* __restrict__ beta,
        float* __restrict__ out,
        int B, int ntiles)
{
    __shared__ __align__(128) float buf[2][TILE_FLOATS];  // 36864 B raw x tiles
    __shared__ __align__(8) uint64_t mbar[2];
    __shared__ float Us[2 * 16 * 17]; // U re|im, rows padded to 17
    __shared__ float pls[SPB * 17];   // pooled, padded
    __shared__ float encs[68];        // enc_w(64) + enc_b(4)
    __shared__ float zsm[SPB * 4];
    __shared__ float stat[8];

    const int tid = threadIdx.x;
    const uint32_t mb0 = smem_u32(&mbar[0]);
    const uint32_t mb1 = smem_u32(&mbar[1]);
    const uint32_t sb0 = smem_u32(&buf[0][0]);
    const uint32_t sb1 = smem_u32(&buf[1][0]);

    // ---- stage encoder ----
    if (tid >= 32 && tid < 96)  encs[tid - 32] = enc_w[tid - 32];
    if (tid >= 96 && tid < 100) encs[64 + tid - 96] = enc_b[tid - 96];

    // ---- mbarrier init + pipeline prologue ----
    if (tid == 0) {
        mbar_init(mb0, 1);
        mbar_init(mb1, 1);
        // fence: make init visible to the async proxy before TMA uses them
        asm volatile("fence.proxy.async.shared::cta;" ::: "memory");
        int t0 = blockIdx.x;
        if (t0 < ntiles) {
            int ns = min(SPB, B - t0 * SPB);
            mbar_expect_tx(mb0, ns * 2304u);
            bulk_ld(sb0, x + (long)t0 * TILE_FLOATS, ns * 2304u, mb0);
        }
        int t1 = blockIdx.x + GRID;
        if (t1 < ntiles) {
            int ns = min(SPB, B - t1 * SPB);
            mbar_expect_tx(mb1, ns * 2304u);
            bulk_ld(sb1, x + (long)t1 * TILE_FLOATS, ns * 2304u, mb1);
        }
    }

    // ---- warp 0: build fixed variational unitary U into smem ----
    if (tid < 16) {
        float re[16], im[16];
#pragma unroll
        for (int b = 0; b < 16; b++) { re[b] = (b == tid) ? 1.f : 0.f; im[b] = 0.f; }
#pragma unroll
        for (int d = 0; d < 2; d++) {
#pragma unroll
            for (int w = 0; w < 4; w++) {
                const int mask = 8 >> w;
                float cx, sx, cy, sy, cz, sz;
                sincosf(0.5f * vp[d * 12 + w * 3 + 0], &sx, &cx);
                sincosf(0.5f * vp[d * 12 + w * 3 + 1], &sy, &cy);
                sincosf(0.5f * vp[d * 12 + w * 3 + 2], &sz, &cz);
#pragma unroll
                for (int b = 0; b < 16; b++) {
                    if (b & mask) continue;
                    const int b1 = b | mask;
                    float r0, i0, r1, i1;
                    r0 = re[b]; i0 = im[b]; r1 = re[b1]; i1 = im[b1];
                    re[b]  = cx * r0 + sx * i1;  im[b]  = cx * i0 - sx * r1;
                    re[b1] = cx * r1 + sx * i0;  im[b1] = cx * i1 - sx * r0;
                    r0 = re[b]; i0 = im[b]; r1 = re[b1]; i1 = im[b1];
                    re[b]  = cy * r0 - sy * r1;  im[b]  = cy * i0 - sy * i1;
                    re[b1] = sy * r0 + cy * r1;  im[b1] = sy * i0 + cy * i1;
                    r0 = re[b]; i0 = im[b]; r1 = re[b1]; i1 = im[b1];
                    re[b]  = cz * r0 + sz * i0;  im[b]  = cz * i0 - sz * r0;
                    re[b1] = cz * r1 - sz * i1;  im[b1] = cz * i1 + sz * r1;
                }
            }
#pragma unroll
            for (int c = 0; c < 4; c++) {
                const int tg = (c + 1) & 3;
                const int mc = 8 >> c, mt = 8 >> tg;
#pragma unroll
                for (int b = 0; b < 16; b++) {
                    if ((b & mc) && !(b & mt)) {
                        const int b1 = b | mt;
                        float tr = re[b], ti = im[b];
                        re[b] = re[b1]; im[b] = im[b1];
                        re[b1] = tr;    im[b1] = ti;
                    }
                }
            }
        }
#pragma unroll
        for (int b = 0; b < 16; b++) {
            Us[b * 17 + tid]       = re[b];
            Us[272 + b * 17 + tid] = im[b];
        }
    }
    __syncthreads();

    // ---- per-thread loop-invariant pooling decomposition ----
    // tid -> (s, w, h): sample, window, half (3 rows each)
    const int ps = tid >> 5;            // 0..7
    const int pw = (tid & 31) >> 1;     // 0..15
    const int phf = tid & 1;            // 0..1
    const int prow0 = (pw >> 2) * 6 + phf * 3;
    const int pcol0 = (pw & 3) * 6;
    const float* const pbase = &buf[0][0] + ps * 576 + prow0 * 24 + pcol0;

    float accS = 0.f, accSS = 0.f;      // BN accumulators (tid<4)

    // ============ persistent tile loop (TMA double-buffered) ============
    int it = 0;
    for (int tile = blockIdx.x; tile < ntiles; tile += GRID, it++) {
        const int cur = it & 1;
        const uint32_t mb = cur ? mb1 : mb0;
        const int samp0 = tile * SPB;
        const int nsamp = min(SPB, B - samp0);

        // ---- wait for this tile's TMA ----
        mbar_wait(mb, (it >> 1) & 1);

        // ---- Phase B: pooling straight from raw smem ----
        {
            const float* p = pbase + cur * TILE_FLOATS;
            float sum = 0.f;
            if (ps < nsamp) {
#pragma unroll
                for (int dy = 0; dy < 3; dy++) {
                    const float2* rowp = (const float2*)(p + dy * 24);
                    float2 a = rowp[0], b = rowp[1], c = rowp[2];
                    sum += a.x + a.y + b.x + b.y + c.x + c.y;
                }
            }
            sum += __shfl_down_sync(0xffffffffu, sum, 1);
            if (phf == 0 && ps < nsamp)
                pls[ps * 17 + pw] = sum * (1.f / 36.f);
        }
        __syncthreads();

        // ---- refill this buffer for tile + 2*GRID (overlaps circuit) ----
        if (tid == 0) {
            const int tn = tile + 2 * GRID;
            if (tn < ntiles) {
                int ns = min(SPB, B - tn * SPB);
                mbar_expect_tx(mb, ns * 2304u);
                bulk_ld(cur ? sb1 : sb0, x + (long)tn * TILE_FLOATS, ns * 2304u, mb);
            }
        }

        // ---- Phase C: circuit, 16 threads / sample (threads 0..127) ----
        const int s = tid >> 4;
        const int j = tid & 15;          // which output amplitude (row of U)
        const int samp = samp0 + s;
        float z0 = 0.f, z1 = 0.f, z2 = 0.f, z3 = 0.f;
        if (tid < 128 && s < nsamp) {
            float ang[4];
#pragma unroll
            for (int i = 0; i < 4; i++) {
                float a = encs[64 + i];
#pragma unroll
                for (int kk = 0; kk < 16; kk++)
                    a = fmaf(encs[i * 16 + kk], pls[s * 17 + kk], a);
                ang[i] = a;
            }
            float cc[4], ss[4];
#pragma unroll
            for (int i = 0; i < 4; i++) __sincosf(0.5f * ang[i], &ss[i], &cc[i]);

            float p01[4], p23[4];
            p01[0] = cc[0] * cc[1]; p01[1] = cc[0] * ss[1];
            p01[2] = ss[0] * cc[1]; p01[3] = ss[0] * ss[1];
            p23[0] = cc[2] * cc[3]; p23[1] = cc[2] * ss[3];
            p23[2] = ss[2] * cc[3]; p23[3] = ss[2] * ss[3];
            float v[16];
#pragma unroll
            for (int b = 0; b < 16; b++) v[b] = p01[b >> 2] * p23[b & 3];

            // one row of U @ psi; (-i)^popc(t) folded at compile time
            float ar = 0.f, ai = 0.f;
#pragma unroll
            for (int t = 0; t < 16; t++) {
                float urv = Us[j * 17 + t], uiv = Us[272 + j * 17 + t];
                const int k4 = __popc(t) & 3;
                if (k4 == 0)      { ar = fmaf(urv,  v[t], ar); ai = fmaf(uiv,  v[t], ai); }
                else if (k4 == 1) { ar = fmaf(uiv,  v[t], ar); ai = fmaf(-urv, v[t], ai); }
                else if (k4 == 2) { ar = fmaf(-urv, v[t], ar); ai = fmaf(-uiv, v[t], ai); }
                else              { ar = fmaf(-uiv, v[t], ar); ai = fmaf(urv,  v[t], ai); }
            }
            float p = ar * ar + ai * ai;
            z0 = (j & 8) ? -p : p;
            z1 = (j & 4) ? -p : p;
            z2 = (j & 2) ? -p : p;
            z3 = (j & 1) ? -p : p;
        }
#pragma unroll
        for (int off = 8; off >= 1; off >>= 1) {
            z0 += __shfl_down_sync(0xffffffffu, z0, off, 16);
            z1 += __shfl_down_sync(0xffffffffu, z1, off, 16);
            z2 += __shfl_down_sync(0xffffffffu, z2, off, 16);
            z3 += __shfl_down_sync(0xffffffffu, z3, off, 16);
        }
        if (tid < 128 && j == 0 && s < nsamp) {
            zsm[s * 4 + 0] = z0; zsm[s * 4 + 1] = z1;
            zsm[s * 4 + 2] = z2; zsm[s * 4 + 3] = z3;
            if (samp < B)
                ((float4*)g_zbuf)[samp] = make_float4(z0, z1, z2, z3);
        }
        __syncthreads();

        // ---- accumulate BN partials (deterministic fixed order) ----
        if (tid < 4) {
            for (int g = 0; g < nsamp; g++) {
                float zv = zsm[g * 4 + tid];
                accS += zv; accSS += zv * zv;
            }
        }
    }

    // ---- publish partials + grid barrier ----
    if (tid < 4) {
        g_part[blockIdx.x * 8 + tid]     = accS;
        g_part[blockIdx.x * 8 + 4 + tid] = accSS;
    }
    __threadfence();
    __syncthreads();
    if (tid == 0) {
        unsigned arr = atomicAdd(&g_bar, 1u) + 1u;
        unsigned target = ((arr + GRID - 1u) / GRID) * GRID;  // this launch's release
        while (*((volatile unsigned*)&g_bar) < target) {}
        __threadfence();
    }
    __syncthreads();

    // ---- redundant-but-deterministic stats reduction (each block) ----
    {
        float* red = &buf[0][0];   // reuse smem
        const int w = tid & 7, rr = tid >> 3;
        float S = 0.f;
        for (int i = rr; i < GRID; i += 32) S += g_part[i * 8 + w];
        red[tid] = S;
        __syncthreads();
#pragma unroll
        for (int step = 128; step >= 8; step >>= 1) {
            if (tid < step) red[tid] += red[tid + step];
            __syncthreads();
        }
        if (tid < 4) {
            float mean = red[tid] / (float)B;
            float var  = red[4 + tid] / (float)B - mean * mean;
            float sc   = gamma[tid] * rsqrtf(var + BN_EPS);
            stat[tid]     = sc;
            stat[4 + tid] = beta[tid] - mean * sc;
        }
        __syncthreads();
    }

    // ---- normalize (z is L2-resident) ----
    const float s0 = stat[0], s1 = stat[1], s2 = stat[2], s3 = stat[3];
    const float h0 = stat[4], h1 = stat[5], h2 = stat[6], h3 = stat[7];
    for (int b = blockIdx.x * NT + tid; b < B; b += GRID * NT) {
        float4 z = ((const float4*)g_zbuf)[b];
        ((float4*)out)[b] = make_float4(fmaf(z.x, s0, h0), fmaf(z.y, s1, h1),
                                        fmaf(z.z, s2, h2), fmaf(z.w, s3, h3));
    }
}

extern "C" void kernel_launch(void* const* d_in, const int* in_sizes, int n_in,
                              void* d_out, int out_size)
{
    const float* x      = (const float*)d_in[0];
    const float* enc_w  = (const float*)d_in[1];
    const float* enc_b  = (const float*)d_in[2];
    const float* vp     = (const float*)d_in[3];
    const float* gamma  = (const float*)d_in[4];
    const float* beta   = (const float*)d_in[5];

    const int B      = in_sizes[0] / 576;   // [B,1,24,24]
    const int ntiles = (B + SPB - 1) / SPB;

    k_fused<<<GRID, NT>>>(x, enc_w, enc_b, vp, gamma, beta,
                          (float*)d_out, B, ntiles);
}

// round 6
// speedup vs baseline: 1.6718x; 1.0874x over previous
#include <cuda_runtime.h>
#include <math.h>
#include <stdint.h>

#define BN_EPS 1e-5f
#define SPB 16                 /* samples per tile */
#define NT 256
#define BPSM 2
#define NSM 148
#define GRID (NSM * BPSM)      /* 296 blocks, guaranteed co-resident */
#define MAXB 65536
#define TILE_FLOATS (SPB * 576)
#define TILE_BYTES  (TILE_FLOATS * 4)   /* 36864 */

// persistent scratch (no allocation allowed)
__device__ float g_zbuf[MAXB * 4];
__device__ float g_part[GRID * 8];
__device__ unsigned g_bar;     // monotone arrival counter (never reset)

__device__ __forceinline__ uint32_t smem_u32(const void* p) {
    uint32_t a;
    asm("{ .reg .u64 t; cvta.to.shared.u64 t, %1; cvt.u32.u64 %0, t; }"
        : "=r"(a) : "l"(p));
    return a;
}
__device__ __forceinline__ void mbar_init(uint32_t m, uint32_t cnt) {
    asm volatile("mbarrier.init.shared.b64 [%0], %1;" :: "r"(m), "r"(cnt) : "memory");
}
__device__ __forceinline__ void mbar_expect_tx(uint32_t m, uint32_t bytes) {
    asm volatile("mbarrier.arrive.expect_tx.shared.b64 _, [%0], %1;"
                 :: "r"(m), "r"(bytes) : "memory");
}
__device__ __forceinline__ void bulk_ld(uint32_t dst, const void* src,
                                        uint32_t bytes, uint32_t m) {
    asm volatile("cp.async.bulk.shared::cluster.global.mbarrier::complete_tx::bytes "
                 "[%0], [%1], %2, [%3];"
                 :: "r"(dst), "l"(src), "r"(bytes), "r"(m) : "memory");
}
__device__ __forceinline__ void mbar_wait(uint32_t m, uint32_t phase) {
    uint32_t done;
    asm volatile("{\n\t.reg .pred p;\n\t"
                 "mbarrier.try_wait.parity.acquire.cta.shared::cta.b64 p, [%1], %2;\n\t"
                 "selp.b32 %0, 1, 0, p;\n\t}"
                 : "=r"(done) : "r"(m), "r"(phase) : "memory");
    if (!done) {
        asm volatile("{\n\t.reg .pred P1;\n\t"
                     "W_%=:\n\t"
                     "mbarrier.try_wait.parity.acquire.cta.shared::cta.b64 P1, [%0], %1, 0x989680;\n\t"
                     "@P1 bra.uni D_%=;\n\t"
                     "bra.uni W_%=;\n\t"
                     "D_%=:\n\t}" :: "r"(m), "r"(phase) : "memory");
    }
}

__global__ void __launch_bounds__(NT, BPSM) k_fused(
        const float* __restrict__ x,
        const float* __restrict__ enc_w,
        const float* __restrict__ enc_b,
        const float* __restrict__ vp,
        const float* __restrict__ gamma,
        const float* __restrict__ beta,
        float* __restrict__ out,
        int B, int ntiles)
{
    __shared__ __align__(128) float buf[2][TILE_FLOATS];  // 73728 B raw x tiles
    __shared__ __align__(8) uint64_t mbar[2];
    __shared__ float Us[2 * 256];     // U re|im (init only)
    __shared__ float pls[SPB * 17];   // pooled, padded
    __shared__ float cs[SPB * 8];     // per-sample cos0..3, sin0..3
    __shared__ float encs[68];        // enc_w(64) + enc_b(4)
    __shared__ float stat[8];

    const int tid = threadIdx.x;
    const uint32_t mb0 = smem_u32(&mbar[0]);
    const uint32_t mb1 = smem_u32(&mbar[1]);
    const uint32_t sbb0 = smem_u32(&buf[0][0]);
    const uint32_t sbb1 = smem_u32(&buf[1][0]);

    // ---- stage encoder ----
    if (tid >= 32 && tid < 96)  encs[tid - 32] = enc_w[tid - 32];
    if (tid >= 96 && tid < 100) encs[64 + tid - 96] = enc_b[tid - 96];

    // ---- mbarrier init + pipeline prologue ----
    if (tid == 0) {
        mbar_init(mb0, 1);
        mbar_init(mb1, 1);
        asm volatile("fence.proxy.async.shared::cta;" ::: "memory");
        int t0 = blockIdx.x;
        if (t0 < ntiles) {
            int ns = min(SPB, B - t0 * SPB);
            mbar_expect_tx(mb0, ns * 2304u);
            bulk_ld(sbb0, x + (long)t0 * TILE_FLOATS, ns * 2304u, mb0);
        }
        int t1 = blockIdx.x + GRID;
        if (t1 < ntiles) {
            int ns = min(SPB, B - t1 * SPB);
            mbar_expect_tx(mb1, ns * 2304u);
            bulk_ld(sbb1, x + (long)t1 * TILE_FLOATS, ns * 2304u, mb1);
        }
    }

    // ---- warp 0: build fixed variational unitary U into smem ----
    if (tid < 16) {
        float re[16], im[16];
#pragma unroll
        for (int b = 0; b < 16; b++) { re[b] = (b == tid) ? 1.f : 0.f; im[b] = 0.f; }
#pragma unroll
        for (int d = 0; d < 2; d++) {
#pragma unroll
            for (int w = 0; w < 4; w++) {
                const int mask = 8 >> w;
                float cx, sx, cy, sy, cz, sz;
                sincosf(0.5f * vp[d * 12 + w * 3 + 0], &sx, &cx);
                sincosf(0.5f * vp[d * 12 + w * 3 + 1], &sy, &cy);
                sincosf(0.5f * vp[d * 12 + w * 3 + 2], &sz, &cz);
#pragma unroll
                for (int b = 0; b < 16; b++) {
                    if (b & mask) continue;
                    const int b1 = b | mask;
                    float r0, i0, r1, i1;
                    r0 = re[b]; i0 = im[b]; r1 = re[b1]; i1 = im[b1];
                    re[b]  = cx * r0 + sx * i1;  im[b]  = cx * i0 - sx * r1;
                    re[b1] = cx * r1 + sx * i0;  im[b1] = cx * i1 - sx * r0;
                    r0 = re[b]; i0 = im[b]; r1 = re[b1]; i1 = im[b1];
                    re[b]  = cy * r0 - sy * r1;  im[b]  = cy * i0 - sy * i1;
                    re[b1] = sy * r0 + cy * r1;  im[b1] = sy * i0 + cy * i1;
                    r0 = re[b]; i0 = im[b]; r1 = re[b1]; i1 = im[b1];
                    re[b]  = cz * r0 + sz * i0;  im[b]  = cz * i0 - sz * r0;
                    re[b1] = cz * r1 - sz * i1;  im[b1] = cz * i1 + sz * r1;
                }
            }
#pragma unroll
            for (int c = 0; c < 4; c++) {
                const int tg = (c + 1) & 3;
                const int mc = 8 >> c, mt = 8 >> tg;
#pragma unroll
                for (int b = 0; b < 16; b++) {
                    if ((b & mc) && !(b & mt)) {
                        const int b1 = b | mt;
                        float tr = re[b], ti = im[b];
                        re[b] = re[b1]; im[b] = im[b1];
                        re[b1] = tr;    im[b1] = ti;
                    }
                }
            }
        }
#pragma unroll
        for (int b = 0; b < 16; b++) {
            Us[b * 16 + tid]       = re[b];
            Us[256 + b * 16 + tid] = im[b];
        }
    }
    __syncthreads();

    // ---- load my U row into registers, sign-folded by (-i)^popc(col) ----
    const int cj = tid & 15;           // my output amplitude (row of U)
    float fr[16], fi[16];
#pragma unroll
    for (int t = 0; t < 16; t++) {
        float urv = Us[cj * 16 + t], uiv = Us[256 + cj * 16 + t];
        const int k4 = __popc(t) & 3;
        if (k4 == 0)      { fr[t] = urv;  fi[t] = uiv;  }
        else if (k4 == 1) { fr[t] = uiv;  fi[t] = -urv; }
        else if (k4 == 2) { fr[t] = -urv; fi[t] = -uiv; }
        else              { fr[t] = -uiv; fi[t] = urv;  }
    }

    // ---- loop-invariant pooling decomposition ----
    // tid -> (half, wpair, wy, s): 2*2*4*16
    const int half  = tid & 1;
    const int wpair = (tid >> 1) & 1;
    const int wy    = (tid >> 2) & 3;
    const int psmp  = tid >> 4;
    const int pf4   = psmp * 144 + (wy * 6 + half * 3) * 6 + wpair * 3;

    const int cs_ = tid >> 4;          // circuit sample
    float accS0 = 0.f, accS1 = 0.f, accS2 = 0.f, accS3 = 0.f;
    float accQ0 = 0.f, accQ1 = 0.f, accQ2 = 0.f, accQ3 = 0.f;

    // ============ persistent tile loop (TMA double-buffered) ============
    int it = 0;
    for (int tile = blockIdx.x; tile < ntiles; tile += GRID, it++) {
        const int cur = it & 1;
        const uint32_t mb = cur ? mb1 : mb0;
        const int samp0 = tile * SPB;
        const int nsamp = min(SPB, B - samp0);

        mbar_wait(mb, (it >> 1) & 1);

        // ---- Phase B: pooling from raw smem (9 LDS.128, shuffle combine) ----
        {
            const float4* p4 = (const float4*)(&buf[cur][0]) + pf4;
            float p0 = 0.f, p1 = 0.f;
            if (psmp < nsamp) {
#pragma unroll
                for (int dy = 0; dy < 3; dy++) {
                    float4 a = p4[dy * 6 + 0];
                    float4 b = p4[dy * 6 + 1];
                    float4 c = p4[dy * 6 + 2];
                    p0 += a.x + a.y + a.z + a.w + b.x + b.y;
                    p1 += b.z + b.w + c.x + c.y + c.z + c.w;
                }
            }
            p0 += __shfl_xor_sync(0xffffffffu, p0, 1);
            p1 += __shfl_xor_sync(0xffffffffu, p1, 1);
            if (half == 0 && psmp < nsamp) {
                float* d = pls + psmp * 17 + wy * 4 + wpair * 2;
                d[0] = p0 * (1.f / 36.f);
                d[1] = p1 * (1.f / 36.f);
            }
        }
        __syncthreads();

        // ---- refill this buffer for tile + 2*GRID (overlaps compute) ----
        if (tid == 0) {
            const int tn = tile + 2 * GRID;
            if (tn < ntiles) {
                int ns = min(SPB, B - tn * SPB);
                mbar_expect_tx(mb, ns * 2304u);
                bulk_ld(cur ? sbb1 : sbb0, x + (long)tn * TILE_FLOATS, ns * 2304u, mb);
            }
        }

        // ---- angles + sincos, once per (sample,wire): 64 threads ----
        if (tid < 64) {
            const int s = tid >> 2, i = tid & 3;
            if (s < nsamp) {
                float a = encs[64 + i];
#pragma unroll
                for (int kk = 0; kk < 16; kk++)
                    a = fmaf(encs[i * 16 + kk], pls[s * 17 + kk], a);
                float sv, cv;
                __sincosf(0.5f * a, &sv, &cv);
                cs[s * 8 + i] = cv;
                cs[s * 8 + 4 + i] = sv;
            }
        }
        __syncthreads();

        // ---- Phase C: circuit, 16 threads / sample, U in registers ----
        float z0 = 0.f, z1 = 0.f, z2 = 0.f, z3 = 0.f;
        if (cs_ < nsamp) {
            float c0 = cs[cs_ * 8 + 0], c1 = cs[cs_ * 8 + 1];
            float c2 = cs[cs_ * 8 + 2], c3 = cs[cs_ * 8 + 3];
            float s0 = cs[cs_ * 8 + 4], s1 = cs[cs_ * 8 + 5];
            float s2 = cs[cs_ * 8 + 6], s3 = cs[cs_ * 8 + 7];
            float p01[4], p23[4];
            p01[0] = c0 * c1; p01[1] = c0 * s1; p01[2] = s0 * c1; p01[3] = s0 * s1;
            p23[0] = c2 * c3; p23[1] = c2 * s3; p23[2] = s2 * c3; p23[3] = s2 * s3;
            float ar = 0.f, ai = 0.f;
#pragma unroll
            for (int t = 0; t < 16; t++) {
                float v = p01[t >> 2] * p23[t & 3];
                ar = fmaf(fr[t], v, ar);
                ai = fmaf(fi[t], v, ai);
            }
            float p = ar * ar + ai * ai;
            z0 = (cj & 8) ? -p : p;
            z1 = (cj & 4) ? -p : p;
            z2 = (cj & 2) ? -p : p;
            z3 = (cj & 1) ? -p : p;
        }
#pragma unroll
        for (int off = 8; off >= 1; off >>= 1) {
            z0 += __shfl_down_sync(0xffffffffu, z0, off, 16);
            z1 += __shfl_down_sync(0xffffffffu, z1, off, 16);
            z2 += __shfl_down_sync(0xffffffffu, z2, off, 16);
            z3 += __shfl_down_sync(0xffffffffu, z3, off, 16);
        }
        if (cj == 0 && cs_ < nsamp) {
            ((float4*)g_zbuf)[samp0 + cs_] = make_float4(z0, z1, z2, z3);
            accS0 += z0; accS1 += z1; accS2 += z2; accS3 += z3;
            accQ0 += z0 * z0; accQ1 += z1 * z1; accQ2 += z2 * z2; accQ3 += z3 * z3;
        }
        // no sync needed: next pooling writes pls, circuit read cs only
    }

    // ---- gather per-sample-slot BN accumulators (deterministic) ----
    __syncthreads();
    if (cj == 0) {
        float* d = pls + cs_ * 8;   // reuse pls as 16x8 scratch
        d[0] = accS0; d[1] = accS1; d[2] = accS2; d[3] = accS3;
        d[4] = accQ0; d[5] = accQ1; d[6] = accQ2; d[7] = accQ3;
    }
    __syncthreads();
    if (tid < 4) {
        float S = 0.f, Q = 0.f;
#pragma unroll
        for (int s = 0; s < 16; s++) {
            S += pls[s * 8 + tid];
            Q += pls[s * 8 + 4 + tid];
        }
        g_part[blockIdx.x * 8 + tid]     = S;
        g_part[blockIdx.x * 8 + 4 + tid] = Q;
    }
    __threadfence();
    __syncthreads();
    if (tid == 0) {
        unsigned arr = atomicAdd(&g_bar, 1u) + 1u;
        unsigned target = ((arr + GRID - 1u) / GRID) * GRID;  // this launch's release
        while (*((volatile unsigned*)&g_bar) < target) {}
        __threadfence();
    }
    __syncthreads();

    // ---- redundant-but-deterministic stats reduction (each block) ----
    {
        float* red = &buf[0][0];   // reuse smem
        const int w = tid & 7, rr = tid >> 3;
        float S = 0.f;
        for (int i = rr; i < GRID; i += 32) S += g_part[i * 8 + w];
        red[tid] = S;
        __syncthreads();
#pragma unroll
        for (int step = 128; step >= 8; step >>= 1) {
            if (tid < step) red[tid] += red[tid + step];
            __syncthreads();
        }
        if (tid < 4) {
            float mean = red[tid] / (float)B;
            float var  = red[4 + tid] / (float)B - mean * mean;
            float sc   = gamma[tid] * rsqrtf(var + BN_EPS);
            stat[tid]     = sc;
            stat[4 + tid] = beta[tid] - mean * sc;
        }
        __syncthreads();
    }

    // ---- normalize (z is L2-resident) ----
    const float n0 = stat[0], n1 = stat[1], n2 = stat[2], n3 = stat[3];
    const float h0 = stat[4], h1 = stat[5], h2 = stat[6], h3 = stat[7];
    for (int b = blockIdx.x * NT + tid; b < B; b += GRID * NT) {
        float4 z = ((const float4*)g_zbuf)[b];
        ((float4*)out)[b] = make_float4(fmaf(z.x, n0, h0), fmaf(z.y, n1, h1),
                                        fmaf(z.z, n2, h2), fmaf(z.w, n3, h3));
    }
}

extern "C" void kernel_launch(void* const* d_in, const int* in_sizes, int n_in,
                              void* d_out, int out_size)
{
    const float* x      = (const float*)d_in[0];
    const float* enc_w  = (const float*)d_in[1];
    const float* enc_b  = (const float*)d_in[2];
    const float* vp     = (const float*)d_in[3];
    const float* gamma  = (const float*)d_in[4];
    const float* beta   = (const float*)d_in[5];

    const int B      = in_sizes[0] / 576;   // [B,1,24,24]
    const int ntiles = (B + SPB - 1) / SPB;

    k_fused<<<GRID, NT>>>(x, enc_w, enc_b, vp, gamma, beta,
                          (float*)d_out, B, ntiles);
}